// round 2
// baseline (speedup 1.0000x reference)
#include <cuda_runtime.h>
#include <cstdint>

#define B_ 8
#define T_ 256
#define H_ 1024
#define V_ 32000
#define M_ (B_*T_)          // 2048 rows = (b,t)

// ---------------- scratch (device globals; no allocation allowed) ----------
__device__ float g_emb[M_*H_];          // gathered embeddings [m][k]
__device__ float g_pre[M_*H_];          // x_t @ W_ih^T + b_ih + b_hh, [b][t][j]
__device__ float g_hs [M_*H_];          // hidden states [b][t][j]
__device__ float g_h  [2*B_*H_];        // double-buffered current h
__device__ float g_bsum[H_];            // b_ih + b_hh
__device__ unsigned g_bar_count;
__device__ unsigned g_bar_gen;

// ---------------- packed fp32x2 FMA (sm_103a FFMA2) ------------------------
__device__ __forceinline__ void ffma2(unsigned long long &c,
                                      unsigned long long a,
                                      unsigned long long b) {
    asm("fma.rn.f32x2 %0, %1, %2, %0;" : "+l"(c) : "l"(a), "l"(b));
}

// ---------------- gather: emb rows + fused bias -----------------------------
__global__ void gather_kernel(const int* __restrict__ x,
                              const float* __restrict__ embed,
                              const float* __restrict__ b_ih,
                              const float* __restrict__ b_hh) {
    int m = blockIdx.x;
    if (m < M_) {
        int tok = x[m];
        const float4* src = reinterpret_cast<const float4*>(embed + (size_t)tok * H_);
        float4* dst = reinterpret_cast<float4*>(g_emb + (size_t)m * H_);
        for (int i = threadIdx.x; i < H_/4; i += blockDim.x) dst[i] = src[i];
    } else {
        for (int i = threadIdx.x; i < H_; i += blockDim.x)
            g_bsum[i] = b_ih[i] + b_hh[i];
    }
}

// ---------------- generic C = A * B^T + bias  (fp32, FFMA2 inner) -----------
// A: [Mdim,K] row-major, B: [Ndim,K] row-major, C: [Mdim,Ndim].
// Mdim%128==0, Ndim%128==0, K%8==0 (true for all uses here).
#define BM 128
#define BN 128
#define BK 8

__global__ __launch_bounds__(256)
void gemm_f32x2(const float* __restrict__ A, const float* __restrict__ Bm,
                const float* __restrict__ bias, float* __restrict__ C,
                int Mdim, int Ndim, int Kdim) {
    __shared__ __align__(16) float  As[2][BK][BM];
    __shared__ __align__(16) float2 Bs[2][BK][BN];   // duplicated (b,b) pairs

    const int tid = threadIdx.x;
    const int bn  = blockIdx.x, bm = blockIdx.y;
    const int tn  = tid & 15;          // 16 threads along n
    const int tm  = tid >> 4;          // 16 threads along m
    const int ar  = tid >> 1;          // 0..127 (tile row for global loads)
    const int ac  = (tid & 1) * 4;     // 0 or 4 (k offset)

    const float* Ag = A  + (size_t)(bm*BM + ar) * Kdim + ac;
    const float* Bg = Bm + (size_t)(bn*BN + ar) * Kdim + ac;

    // preload tile 0
    {
        float4 a = *reinterpret_cast<const float4*>(Ag);
        float4 b = *reinterpret_cast<const float4*>(Bg);
        As[0][ac+0][ar] = a.x; As[0][ac+1][ar] = a.y;
        As[0][ac+2][ar] = a.z; As[0][ac+3][ar] = a.w;
        Bs[0][ac+0][ar] = make_float2(b.x, b.x);
        Bs[0][ac+1][ar] = make_float2(b.y, b.y);
        Bs[0][ac+2][ar] = make_float2(b.z, b.z);
        Bs[0][ac+3][ar] = make_float2(b.w, b.w);
    }
    __syncthreads();

    unsigned long long acc[4][8];
    #pragma unroll
    for (int i = 0; i < 4; i++)
        #pragma unroll
        for (int j = 0; j < 8; j++) acc[i][j] = 0ull;

    const int NK = Kdim / BK;
    for (int kt = 0; kt < NK; ++kt) {
        const int cur = kt & 1, nxt = cur ^ 1;
        float4 a2, b2;
        const bool more = (kt + 1 < NK);
        if (more) {
            a2 = *reinterpret_cast<const float4*>(Ag + (kt+1)*BK);
            b2 = *reinterpret_cast<const float4*>(Bg + (kt+1)*BK);
        }
        #pragma unroll
        for (int k = 0; k < BK; k++) {
            ulonglong2 ap0 = *reinterpret_cast<const ulonglong2*>(&As[cur][k][tm*8]);
            ulonglong2 ap1 = *reinterpret_cast<const ulonglong2*>(&As[cur][k][tm*8+4]);
            const ulonglong2* bpp = reinterpret_cast<const ulonglong2*>(&Bs[cur][k][tn*8]);
            unsigned long long ap[4] = {ap0.x, ap0.y, ap1.x, ap1.y};
            unsigned long long bp[8];
            #pragma unroll
            for (int q = 0; q < 4; q++) { ulonglong2 t2 = bpp[q]; bp[2*q] = t2.x; bp[2*q+1] = t2.y; }
            #pragma unroll
            for (int i = 0; i < 4; i++)
                #pragma unroll
                for (int j = 0; j < 8; j++)
                    ffma2(acc[i][j], ap[i], bp[j]);
        }
        if (more) {
            As[nxt][ac+0][ar] = a2.x; As[nxt][ac+1][ar] = a2.y;
            As[nxt][ac+2][ar] = a2.z; As[nxt][ac+3][ar] = a2.w;
            Bs[nxt][ac+0][ar] = make_float2(b2.x, b2.x);
            Bs[nxt][ac+1][ar] = make_float2(b2.y, b2.y);
            Bs[nxt][ac+2][ar] = make_float2(b2.z, b2.z);
            Bs[nxt][ac+3][ar] = make_float2(b2.w, b2.w);
        }
        __syncthreads();
    }

    // epilogue
    float bvals[8];
    #pragma unroll
    for (int j = 0; j < 8; j++) bvals[j] = bias[bn*BN + tn*8 + j];
    #pragma unroll
    for (int i = 0; i < 4; i++) {
        const int m0 = bm*BM + tm*8 + 2*i;
        #pragma unroll
        for (int j = 0; j < 8; j++) {
            float2 v = *reinterpret_cast<float2*>(&acc[i][j]);
            const int n = bn*BN + tn*8 + j;
            C[(size_t)m0     * Ndim + n] = v.x + bvals[j];
            C[(size_t)(m0+1) * Ndim + n] = v.y + bvals[j];
        }
    }
}

// ---------------- persistent scan kernel -----------------------------------
#define SCAN_BLOCKS 128

__device__ __forceinline__ void grid_barrier(int nb) {
    __syncthreads();
    if (threadIdx.x == 0) {
        unsigned g = *((volatile unsigned*)&g_bar_gen);
        __threadfence();
        if (atomicAdd(&g_bar_count, 1) == (unsigned)(nb - 1)) {
            g_bar_count = 0;
            __threadfence();
            *((volatile unsigned*)&g_bar_gen) = g + 1;
        } else {
            while (*((volatile unsigned*)&g_bar_gen) == g) { __nanosleep(32); }
        }
        __threadfence();
    }
    __syncthreads();
}

__global__ __launch_bounds__(256)
void scan_kernel(const float* __restrict__ Whh, float* __restrict__ hfinal) {
    __shared__ __align__(16) float hsh[B_*H_];   // 32 KB
    const int tid  = threadIdx.x;
    const int warp = tid >> 5;
    const int lane = tid & 31;
    const int j    = blockIdx.x * 8 + warp;      // one output column per warp

    // W_hh row j stays in registers for all 256 steps.
    float4 w[8];
    const float4* wrow = reinterpret_cast<const float4*>(Whh + (size_t)j * H_);
    #pragma unroll
    for (int i = 0; i < 8; i++) w[i] = wrow[lane + 32*i];

    // zero h buffer 0
    for (int idx = blockIdx.x*256 + tid; idx < B_*H_; idx += SCAN_BLOCKS*256)
        g_h[idx] = 0.f;
    grid_barrier(SCAN_BLOCKS);

    for (int t = 0; t < T_; t++) {
        const int rp = t & 1, wp = rp ^ 1;
        // stage current h into shared
        float4* hs4 = reinterpret_cast<float4*>(hsh);
        const float4* hg4 = reinterpret_cast<const float4*>(g_h + rp*B_*H_);
        #pragma unroll
        for (int i = 0; i < (B_*H_/4)/256; i++) hs4[tid + 256*i] = hg4[tid + 256*i];
        __syncthreads();

        float acc[B_];
        #pragma unroll
        for (int b = 0; b < B_; b++) acc[b] = 0.f;
        #pragma unroll
        for (int i = 0; i < 8; i++) {
            const float4 wv = w[i];
            #pragma unroll
            for (int b = 0; b < B_; b++) {
                const float4 hv = *reinterpret_cast<const float4*>(&hsh[b*H_ + lane*4 + 128*i]);
                acc[b] += wv.x*hv.x + wv.y*hv.y + wv.z*hv.z + wv.w*hv.w;
            }
        }
        #pragma unroll
        for (int b = 0; b < B_; b++) {
            #pragma unroll
            for (int off = 16; off; off >>= 1)
                acc[b] += __shfl_xor_sync(0xffffffffu, acc[b], off);
        }
        if (lane < B_) {
            float a = acc[0];
            if (lane == 1) a = acc[1];
            if (lane == 2) a = acc[2];
            if (lane == 3) a = acc[3];
            if (lane == 4) a = acc[4];
            if (lane == 5) a = acc[5];
            if (lane == 6) a = acc[6];
            if (lane == 7) a = acc[7];
            const float hn = tanhf(a + g_pre[(size_t)lane*(T_*H_) + t*H_ + j]);
            g_h[wp*B_*H_ + lane*H_ + j] = hn;
            g_hs[(size_t)lane*(T_*H_) + t*H_ + j] = hn;
            if (t == T_-1) hfinal[lane*H_ + j] = hn;
        }
        __threadfence();
        grid_barrier(SCAN_BLOCKS);
    }
}

// ---------------- launch ----------------------------------------------------
extern "C" void kernel_launch(void* const* d_in, const int* in_sizes, int n_in,
                              void* d_out, int out_size) {
    const int*   x     = (const int*)  d_in[0];
    const float* embed = (const float*)d_in[1];
    const float* W_ih  = (const float*)d_in[2];
    const float* b_ih  = (const float*)d_in[3];
    const float* W_hh  = (const float*)d_in[4];
    const float* b_hh  = (const float*)d_in[5];
    const float* W_out = (const float*)d_in[6];
    const float* b_out = (const float*)d_in[7];
    float* out = (float*)d_out;

    void *p_emb, *p_pre, *p_hs, *p_bsum;
    cudaGetSymbolAddress(&p_emb,  g_emb);
    cudaGetSymbolAddress(&p_pre,  g_pre);
    cudaGetSymbolAddress(&p_hs,   g_hs);
    cudaGetSymbolAddress(&p_bsum, g_bsum);

    // 1) gather embeddings + fused bias
    gather_kernel<<<M_ + 1, 256>>>(x, embed, b_ih, b_hh);

    // 2) pre = emb @ W_ih^T + (b_ih + b_hh)   [2048 x 1024]
    gemm_f32x2<<<dim3(H_/BN, M_/BM), 256>>>(
        (const float*)p_emb, W_ih, (const float*)p_bsum, (float*)p_pre,
        M_, H_, H_);

    // 3) persistent recurrent scan; writes g_hs and h_final tail of d_out
    scan_kernel<<<SCAN_BLOCKS, 256>>>(W_hh, out + (size_t)M_ * V_);

    // 4) outputs = hs @ W_out^T + b_out   [2048 x 32000]
    gemm_f32x2<<<dim3(V_/BN, M_/BM), 256>>>(
        (const float*)p_hs, W_out, b_out, out,
        M_, V_, H_);
}

// round 5
// speedup vs baseline: 6.1870x; 6.1870x over previous
#include <cuda_runtime.h>
#include <cuda_bf16.h>
#include <cstdint>

#define B_ 8
#define T_ 256
#define H_ 1024
#define V_ 32000
#define M_ (B_*T_)          // 2048 rows = (b,t)

// ---------------- scratch (device globals; no allocation allowed) ----------
__device__ __align__(16) __nv_bfloat16 g_Ahi[M_*H_];           // emb hi
__device__ __align__(16) __nv_bfloat16 g_Alo[M_*H_];           // emb lo
__device__ __align__(16) __nv_bfloat16 g_Wih_hi[H_*H_];
__device__ __align__(16) __nv_bfloat16 g_Wih_lo[H_*H_];
__device__ __align__(16) __nv_bfloat16 g_Wo_hi[(size_t)V_*H_];
__device__ __align__(16) __nv_bfloat16 g_Wo_lo[(size_t)V_*H_];
__device__ __align__(16) __nv_bfloat16 g_Hhi[M_*H_];           // hs hi
__device__ __align__(16) __nv_bfloat16 g_Hlo[M_*H_];           // hs lo
__device__ __align__(16) float g_pre[M_*H_];   // x_t @ W_ih^T + b_ih + b_hh
__device__ __align__(16) float g_hs [M_*H_];   // hidden states [b][t][j]
__device__ __align__(16) float g_h  [2*B_*H_]; // double-buffered current h
__device__ float g_bsum[H_];
__device__ unsigned g_bar_count;
__device__ unsigned g_bar_gen;

// ---------------- PTX helpers (arch-neutral: ldmatrix/mma/cp.async) --------
__device__ __forceinline__ uint32_t smem_to_u32(const void* p) {
    uint32_t a;
    asm("{ .reg .u64 t; cvta.to.shared.u64 t, %1; cvt.u32.u64 %0, t; }"
        : "=r"(a) : "l"(p));
    return a;
}
__device__ __forceinline__ void ldsm_x4(uint32_t* r, uint32_t addr) {
    asm volatile("ldmatrix.sync.aligned.m8n8.x4.shared.b16 {%0,%1,%2,%3}, [%4];"
        : "=r"(r[0]), "=r"(r[1]), "=r"(r[2]), "=r"(r[3]) : "r"(addr));
}
__device__ __forceinline__ void mma_bf16(float* d, const uint32_t* a, const uint32_t* b) {
    asm volatile(
        "mma.sync.aligned.m16n8k16.row.col.f32.bf16.bf16.f32 "
        "{%0,%1,%2,%3}, {%4,%5,%6,%7}, {%8,%9}, {%0,%1,%2,%3};"
        : "+f"(d[0]), "+f"(d[1]), "+f"(d[2]), "+f"(d[3])
        : "r"(a[0]), "r"(a[1]), "r"(a[2]), "r"(a[3]), "r"(b[0]), "r"(b[1]));
}
__device__ __forceinline__ void cp16(uint32_t saddr, const void* g) {
    asm volatile("cp.async.cg.shared.global [%0], [%1], 16;" :: "r"(saddr), "l"(g));
}
#define CP_COMMIT() asm volatile("cp.async.commit_group;" ::: "memory")
#define CP_WAIT0()  asm volatile("cp.async.wait_group 0;" ::: "memory")
#define CP_WAIT1()  asm volatile("cp.async.wait_group 1;" ::: "memory")

// ---------------- gather: emb rows split to bf16 hi/lo + fused bias --------
__global__ void gather_kernel(const int* __restrict__ x,
                              const float* __restrict__ embed,
                              const float* __restrict__ b_ih,
                              const float* __restrict__ b_hh) {
    int m = blockIdx.x;
    if (m < M_) {
        int tok = x[m];
        for (int i = threadIdx.x; i < H_; i += blockDim.x) {
            float v = embed[(size_t)tok * H_ + i];
            __nv_bfloat16 h = __float2bfloat16(v);
            g_Ahi[(size_t)m * H_ + i] = h;
            g_Alo[(size_t)m * H_ + i] = __float2bfloat16(v - __bfloat162float(h));
        }
    } else {
        for (int i = threadIdx.x; i < H_; i += blockDim.x)
            g_bsum[i] = b_ih[i] + b_hh[i];
    }
}

// ---------------- fp32 -> bf16 hi/lo split ---------------------------------
__global__ void split_kernel(const float* __restrict__ src,
                             __nv_bfloat16* __restrict__ hi,
                             __nv_bfloat16* __restrict__ lo, size_t n) {
    size_t i = ((size_t)blockIdx.x * blockDim.x + threadIdx.x) * 4;
    if (i < n) {
        float4 v = *reinterpret_cast<const float4*>(src + i);
        __nv_bfloat16 h0 = __float2bfloat16(v.x), h1 = __float2bfloat16(v.y);
        __nv_bfloat16 h2 = __float2bfloat16(v.z), h3 = __float2bfloat16(v.w);
        __nv_bfloat162 hh0 = {h0, h1}, hh1 = {h2, h3};
        __nv_bfloat162 ll0 = {__float2bfloat16(v.x - __bfloat162float(h0)),
                              __float2bfloat16(v.y - __bfloat162float(h1))};
        __nv_bfloat162 ll1 = {__float2bfloat16(v.z - __bfloat162float(h2)),
                              __float2bfloat16(v.w - __bfloat162float(h3))};
        *reinterpret_cast<__nv_bfloat162*>(hi + i)     = hh0;
        *reinterpret_cast<__nv_bfloat162*>(hi + i + 2) = hh1;
        *reinterpret_cast<__nv_bfloat162*>(lo + i)     = ll0;
        *reinterpret_cast<__nv_bfloat162*>(lo + i + 2) = ll1;
    }
}

// ---------------- split-bf16 HMMA GEMM -------------------------------------
// C[r][c] = sum_k A[r][k]*B[c][k] + bias[c] via Ahi*Bhi + Ahi*Blo + Alo*Bhi.
// A: [Mrows][H_] row-major, B: [Ncols][H_] row-major.  K = H_ = 1024 fixed.
#define GBM 128
#define GBN 128
#define GBK 32
#define NKC (H_/GBK)                    // 32 k-chunks
#define LDT 40                          // smem row stride in bf16 (pad 8)
#define MAT_B (GBM*LDT*2)               // 10240 bytes per matrix tile
#define STAGE_B (4*MAT_B)               // 40960 bytes per stage
#define SMEM_B (2*STAGE_B)              // 81920 bytes total

__global__ __launch_bounds__(256, 1)
void gemm_mma(const __nv_bfloat16* __restrict__ Ahi, const __nv_bfloat16* __restrict__ Alo,
              const __nv_bfloat16* __restrict__ Bhi, const __nv_bfloat16* __restrict__ Blo,
              const float* __restrict__ bias, float* __restrict__ C, int Ndim) {
    extern __shared__ __align__(16) char sm[];
    const uint32_t sb = smem_to_u32(sm);
    const int tid  = threadIdx.x;
    const int lane = tid & 31, wid = tid >> 5;
    const int wm = wid & 3, wn = wid >> 2;      // warp tile: rows 32*wm, cols 64*wn
    const int bm = blockIdx.x, bn = blockIdx.y;

    // ---- prefetch chunk c into stage c&1 (8 x cp.async.16B per thread) ----
    auto prefetch = [&](int c) {
        const uint32_t st = sb + (uint32_t)(c & 1) * STAGE_B;
        const int kcol = c * GBK;
        #pragma unroll
        for (int q = 0; q < 2; q++) {
            const int u = tid + 256*q;
            const int r = u >> 2, sg = u & 3;
            const uint32_t so = (uint32_t)(r*LDT + sg*8) * 2;
            const size_t goA = (size_t)(bm*GBM + r) * H_ + kcol + sg*8;
            const size_t goB = (size_t)(bn*GBN + r) * H_ + kcol + sg*8;
            cp16(st + 0*MAT_B + so, Ahi + goA);
            cp16(st + 1*MAT_B + so, Alo + goA);
            cp16(st + 2*MAT_B + so, Bhi + goB);
            cp16(st + 3*MAT_B + so, Blo + goB);
        }
    };

    float acc[2][8][4];
    #pragma unroll
    for (int i = 0; i < 2; i++)
        #pragma unroll
        for (int j = 0; j < 8; j++)
            #pragma unroll
            for (int q = 0; q < 4; q++) acc[i][j][q] = 0.f;

    prefetch(0); CP_COMMIT();

    for (int c = 0; c < NKC; c++) {
        if (c + 1 < NKC) { prefetch(c + 1); CP_COMMIT(); CP_WAIT1(); }
        else             { CP_WAIT0(); }
        __syncthreads();

        const uint32_t st = sb + (uint32_t)(c & 1) * STAGE_B;
        #pragma unroll
        for (int ks = 0; ks < 2; ks++) {
            // A fragments (hi & lo): rows wm*32 + f*16 + lane%16, k seg lane/16
            uint32_t ah[8], al[8];
            #pragma unroll
            for (int f = 0; f < 2; f++) {
                const int row = wm*32 + f*16 + (lane & 15);
                const uint32_t off = (uint32_t)(row*LDT + ks*16 + (lane >> 4)*8) * 2;
                ldsm_x4(ah + 4*f, st + 0*MAT_B + off);
                ldsm_x4(al + 4*f, st + 1*MAT_B + off);
            }
            // B fragments (hi & lo): x4 loads two n8 frags each
            uint32_t bh[16], bl[16];
            #pragma unroll
            for (int p = 0; p < 4; p++) {
                const int n  = wn*64 + p*16 + ((lane >> 4) << 3) + (lane & 7);
                const int kc = ks*16 + ((lane >> 3) & 1) * 8;
                const uint32_t off = (uint32_t)(n*LDT + kc) * 2;
                ldsm_x4(bh + 4*p, st + 2*MAT_B + off);
                ldsm_x4(bl + 4*p, st + 3*MAT_B + off);
            }
            // 3-pass split-precision MMA into shared fp32 accumulators
            #pragma unroll
            for (int fm = 0; fm < 2; fm++)
                #pragma unroll
                for (int fn = 0; fn < 8; fn++) {
                    mma_bf16(acc[fm][fn], ah + 4*fm, bh + 2*fn);
                    mma_bf16(acc[fm][fn], ah + 4*fm, bl + 2*fn);
                    mma_bf16(acc[fm][fn], al + 4*fm, bh + 2*fn);
                }
        }
        __syncthreads();
    }

    // ---- epilogue: acc + bias -> C ----
    #pragma unroll
    for (int fm = 0; fm < 2; fm++) {
        const int row = bm*GBM + wm*32 + fm*16 + (lane >> 2);
        #pragma unroll
        for (int fn = 0; fn < 8; fn++) {
            const int col = bn*GBN + wn*64 + fn*8 + (lane & 3)*2;
            const float2 bv = *reinterpret_cast<const float2*>(bias + col);
            float2 o0, o1;
            o0.x = acc[fm][fn][0] + bv.x; o0.y = acc[fm][fn][1] + bv.y;
            o1.x = acc[fm][fn][2] + bv.x; o1.y = acc[fm][fn][3] + bv.y;
            *reinterpret_cast<float2*>(C + (size_t)row     * Ndim + col) = o0;
            *reinterpret_cast<float2*>(C + (size_t)(row+8) * Ndim + col) = o1;
        }
    }
}

// ---------------- persistent scan kernel (unchanged, passing) --------------
#define SCAN_BLOCKS 128

__device__ __forceinline__ void grid_barrier(int nb) {
    __syncthreads();
    if (threadIdx.x == 0) {
        unsigned g = *((volatile unsigned*)&g_bar_gen);
        __threadfence();
        if (atomicAdd(&g_bar_count, 1) == (unsigned)(nb - 1)) {
            g_bar_count = 0;
            __threadfence();
            *((volatile unsigned*)&g_bar_gen) = g + 1;
        } else {
            while (*((volatile unsigned*)&g_bar_gen) == g) { __nanosleep(32); }
        }
        __threadfence();
    }
    __syncthreads();
}

__global__ __launch_bounds__(256)
void scan_kernel(const float* __restrict__ Whh, float* __restrict__ hfinal) {
    __shared__ __align__(16) float hsh[B_*H_];
    const int tid  = threadIdx.x;
    const int warp = tid >> 5;
    const int lane = tid & 31;
    const int j    = blockIdx.x * 8 + warp;

    float4 w[8];
    const float4* wrow = reinterpret_cast<const float4*>(Whh + (size_t)j * H_);
    #pragma unroll
    for (int i = 0; i < 8; i++) w[i] = wrow[lane + 32*i];

    for (int idx = blockIdx.x*256 + tid; idx < B_*H_; idx += SCAN_BLOCKS*256)
        g_h[idx] = 0.f;
    grid_barrier(SCAN_BLOCKS);

    for (int t = 0; t < T_; t++) {
        const int rp = t & 1, wp = rp ^ 1;
        float4* hs4 = reinterpret_cast<float4*>(hsh);
        const float4* hg4 = reinterpret_cast<const float4*>(g_h + rp*B_*H_);
        #pragma unroll
        for (int i = 0; i < (B_*H_/4)/256; i++) hs4[tid + 256*i] = hg4[tid + 256*i];
        __syncthreads();

        float acc[B_];
        #pragma unroll
        for (int b = 0; b < B_; b++) acc[b] = 0.f;
        #pragma unroll
        for (int i = 0; i < 8; i++) {
            const float4 wv = w[i];
            #pragma unroll
            for (int b = 0; b < B_; b++) {
                const float4 hv = *reinterpret_cast<const float4*>(&hsh[b*H_ + lane*4 + 128*i]);
                acc[b] += wv.x*hv.x + wv.y*hv.y + wv.z*hv.z + wv.w*hv.w;
            }
        }
        #pragma unroll
        for (int b = 0; b < B_; b++) {
            #pragma unroll
            for (int off = 16; off; off >>= 1)
                acc[b] += __shfl_xor_sync(0xffffffffu, acc[b], off);
        }
        if (lane < B_) {
            float a = acc[0];
            if (lane == 1) a = acc[1];
            if (lane == 2) a = acc[2];
            if (lane == 3) a = acc[3];
            if (lane == 4) a = acc[4];
            if (lane == 5) a = acc[5];
            if (lane == 6) a = acc[6];
            if (lane == 7) a = acc[7];
            const float hn = tanhf(a + g_pre[(size_t)lane*(T_*H_) + t*H_ + j]);
            g_h[wp*B_*H_ + lane*H_ + j] = hn;
            g_hs[(size_t)lane*(T_*H_) + t*H_ + j] = hn;
            if (t == T_-1) hfinal[lane*H_ + j] = hn;
        }
        __threadfence();
        grid_barrier(SCAN_BLOCKS);
    }
}

// ---------------- launch ----------------------------------------------------
extern "C" void kernel_launch(void* const* d_in, const int* in_sizes, int n_in,
                              void* d_out, int out_size) {
    const int*   x     = (const int*)  d_in[0];
    const float* embed = (const float*)d_in[1];
    const float* W_ih  = (const float*)d_in[2];
    const float* b_ih  = (const float*)d_in[3];
    const float* W_hh  = (const float*)d_in[4];
    const float* b_hh  = (const float*)d_in[5];
    const float* W_out = (const float*)d_in[6];
    const float* b_out = (const float*)d_in[7];
    float* out = (float*)d_out;

    void *p_Ahi, *p_Alo, *p_Wih_hi, *p_Wih_lo, *p_Wo_hi, *p_Wo_lo;
    void *p_Hhi, *p_Hlo, *p_pre, *p_hs, *p_bsum;
    cudaGetSymbolAddress(&p_Ahi, g_Ahi);       cudaGetSymbolAddress(&p_Alo, g_Alo);
    cudaGetSymbolAddress(&p_Wih_hi, g_Wih_hi); cudaGetSymbolAddress(&p_Wih_lo, g_Wih_lo);
    cudaGetSymbolAddress(&p_Wo_hi, g_Wo_hi);   cudaGetSymbolAddress(&p_Wo_lo, g_Wo_lo);
    cudaGetSymbolAddress(&p_Hhi, g_Hhi);       cudaGetSymbolAddress(&p_Hlo, g_Hlo);
    cudaGetSymbolAddress(&p_pre, g_pre);       cudaGetSymbolAddress(&p_hs, g_hs);
    cudaGetSymbolAddress(&p_bsum, g_bsum);

    cudaFuncSetAttribute(gemm_mma, cudaFuncAttributeMaxDynamicSharedMemorySize, SMEM_B);

    // 1) gather embeddings (split to bf16 hi/lo) + fused bias
    gather_kernel<<<M_ + 1, 256>>>(x, embed, b_ih, b_hh);

    // 2) split weights to bf16 hi/lo
    split_kernel<<<(H_*H_/4 + 255)/256, 256>>>(W_ih,
        (__nv_bfloat16*)p_Wih_hi, (__nv_bfloat16*)p_Wih_lo, (size_t)H_*H_);
    split_kernel<<<(int)(((size_t)V_*H_/4 + 255)/256), 256>>>(W_out,
        (__nv_bfloat16*)p_Wo_hi, (__nv_bfloat16*)p_Wo_lo, (size_t)V_*H_);

    // 3) pre = emb @ W_ih^T + (b_ih + b_hh)   [2048 x 1024]
    gemm_mma<<<dim3(M_/GBM, H_/GBN), 256, SMEM_B>>>(
        (const __nv_bfloat16*)p_Ahi, (const __nv_bfloat16*)p_Alo,
        (const __nv_bfloat16*)p_Wih_hi, (const __nv_bfloat16*)p_Wih_lo,
        (const float*)p_bsum, (float*)p_pre, H_);

    // 4) persistent recurrent scan; writes g_hs and h_final tail of d_out
    scan_kernel<<<SCAN_BLOCKS, 256>>>(W_hh, out + (size_t)M_ * V_);

    // 5) split hidden states to bf16 hi/lo
    split_kernel<<<(M_*H_/4 + 255)/256, 256>>>((const float*)p_hs,
        (__nv_bfloat16*)p_Hhi, (__nv_bfloat16*)p_Hlo, (size_t)M_*H_);

    // 6) outputs = hs @ W_out^T + b_out   [2048 x 32000]
    gemm_mma<<<dim3(M_/GBM, V_/GBN), 256, SMEM_B>>>(
        (const __nv_bfloat16*)p_Hhi, (const __nv_bfloat16*)p_Hlo,
        (const __nv_bfloat16*)p_Wo_hi, (const __nv_bfloat16*)p_Wo_lo,
        b_out, out, V_);
}

// round 6
// speedup vs baseline: 6.8009x; 1.0992x over previous
#include <cuda_runtime.h>
#include <cuda_bf16.h>
#include <cstdint>

#define B_ 8
#define T_ 256
#define H_ 1024
#define V_ 32000
#define M_ (B_*T_)          // 2048 rows = (b,t)

// ---------------- scratch (device globals; no allocation allowed) ----------
__device__ __align__(16) __nv_bfloat16 g_Ahi[M_*H_];           // emb hi
__device__ __align__(16) __nv_bfloat16 g_Alo[M_*H_];           // emb lo
__device__ __align__(16) __nv_bfloat16 g_Wih_hi[H_*H_];
__device__ __align__(16) __nv_bfloat16 g_Wih_lo[H_*H_];
__device__ __align__(16) __nv_bfloat16 g_Wo_hi[(size_t)V_*H_];
__device__ __align__(16) __nv_bfloat16 g_Wo_lo[(size_t)V_*H_];
__device__ __align__(16) __nv_bfloat16 g_Hhi[M_*H_];           // hs hi
__device__ __align__(16) __nv_bfloat16 g_Hlo[M_*H_];           // hs lo
__device__ __align__(16) float g_pre[M_*H_];   // x_t @ W_ih^T + b_ih + b_hh
__device__ __align__(16) float g_hs [M_*H_];   // hidden states [b][t][j]
__device__ __align__(16) float g_h  [2*B_*H_]; // double-buffered current h
__device__ float g_bsum[H_];
__device__ unsigned g_bar_count;
__device__ unsigned g_bar_gen;

// ---------------- PTX helpers (arch-neutral: ldmatrix/mma/cp.async) --------
__device__ __forceinline__ uint32_t smem_to_u32(const void* p) {
    uint32_t a;
    asm("{ .reg .u64 t; cvta.to.shared.u64 t, %1; cvt.u32.u64 %0, t; }"
        : "=r"(a) : "l"(p));
    return a;
}
__device__ __forceinline__ void ldsm_x4(uint32_t* r, uint32_t addr) {
    asm volatile("ldmatrix.sync.aligned.m8n8.x4.shared.b16 {%0,%1,%2,%3}, [%4];"
        : "=r"(r[0]), "=r"(r[1]), "=r"(r[2]), "=r"(r[3]) : "r"(addr));
}
__device__ __forceinline__ void mma_bf16(float* d, const uint32_t* a, const uint32_t* b) {
    asm volatile(
        "mma.sync.aligned.m16n8k16.row.col.f32.bf16.bf16.f32 "
        "{%0,%1,%2,%3}, {%4,%5,%6,%7}, {%8,%9}, {%0,%1,%2,%3};"
        : "+f"(d[0]), "+f"(d[1]), "+f"(d[2]), "+f"(d[3])
        : "r"(a[0]), "r"(a[1]), "r"(a[2]), "r"(a[3]), "r"(b[0]), "r"(b[1]));
}
__device__ __forceinline__ void cp16(uint32_t saddr, const void* g) {
    asm volatile("cp.async.cg.shared.global [%0], [%1], 16;" :: "r"(saddr), "l"(g));
}
#define CP_COMMIT() asm volatile("cp.async.commit_group;" ::: "memory")
#define CP_WAIT0()  asm volatile("cp.async.wait_group 0;" ::: "memory")
#define CP_WAIT1()  asm volatile("cp.async.wait_group 1;" ::: "memory")

// ---------------- gather: emb rows split to bf16 hi/lo + fused bias --------
__global__ void gather_kernel(const int* __restrict__ x,
                              const float* __restrict__ embed,
                              const float* __restrict__ b_ih,
                              const float* __restrict__ b_hh) {
    int m = blockIdx.x;
    if (m < M_) {
        int tok = x[m];
        for (int i = threadIdx.x; i < H_; i += blockDim.x) {
            float v = embed[(size_t)tok * H_ + i];
            __nv_bfloat16 h = __float2bfloat16(v);
            g_Ahi[(size_t)m * H_ + i] = h;
            g_Alo[(size_t)m * H_ + i] = __float2bfloat16(v - __bfloat162float(h));
        }
    } else {
        for (int i = threadIdx.x; i < H_; i += blockDim.x)
            g_bsum[i] = b_ih[i] + b_hh[i];
    }
}

// ---------------- fp32 -> bf16 hi/lo split ---------------------------------
__global__ void split_kernel(const float* __restrict__ src,
                             __nv_bfloat16* __restrict__ hi,
                             __nv_bfloat16* __restrict__ lo, size_t n) {
    size_t i = ((size_t)blockIdx.x * blockDim.x + threadIdx.x) * 4;
    if (i < n) {
        float4 v = *reinterpret_cast<const float4*>(src + i);
        __nv_bfloat16 h0 = __float2bfloat16(v.x), h1 = __float2bfloat16(v.y);
        __nv_bfloat16 h2 = __float2bfloat16(v.z), h3 = __float2bfloat16(v.w);
        __nv_bfloat162 hh0 = {h0, h1}, hh1 = {h2, h3};
        __nv_bfloat162 ll0 = {__float2bfloat16(v.x - __bfloat162float(h0)),
                              __float2bfloat16(v.y - __bfloat162float(h1))};
        __nv_bfloat162 ll1 = {__float2bfloat16(v.z - __bfloat162float(h2)),
                              __float2bfloat16(v.w - __bfloat162float(h3))};
        *reinterpret_cast<__nv_bfloat162*>(hi + i)     = hh0;
        *reinterpret_cast<__nv_bfloat162*>(hi + i + 2) = hh1;
        *reinterpret_cast<__nv_bfloat162*>(lo + i)     = ll0;
        *reinterpret_cast<__nv_bfloat162*>(lo + i + 2) = ll1;
    }
}

// ---------------- split-bf16 HMMA GEMM -------------------------------------
// C[r][c] = sum_k A[r][k]*B[c][k] + bias[c] via Ahi*Bhi + Ahi*Blo + Alo*Bhi.
// A: [Mrows][H_] row-major, B: [Ncols][H_] row-major.  K = H_ = 1024 fixed.
#define GBM 128
#define GBN 128
#define GBK 32
#define NKC (H_/GBK)                    // 32 k-chunks
#define LDT 40                          // smem row stride in bf16 (pad 8)
#define MAT_B (GBM*LDT*2)               // 10240 bytes per matrix tile
#define STAGE_B (4*MAT_B)               // 40960 bytes per stage
#define SMEM_B (2*STAGE_B)              // 81920 bytes total

__global__ __launch_bounds__(256, 2)
void gemm_mma(const __nv_bfloat16* __restrict__ Ahi, const __nv_bfloat16* __restrict__ Alo,
              const __nv_bfloat16* __restrict__ Bhi, const __nv_bfloat16* __restrict__ Blo,
              const float* __restrict__ bias, float* __restrict__ C, int Ndim) {
    extern __shared__ __align__(16) char sm[];
    const uint32_t sb = smem_to_u32(sm);
    const int tid  = threadIdx.x;
    const int lane = tid & 31, wid = tid >> 5;
    const int wm = wid & 3, wn = wid >> 2;      // warp tile: rows 32*wm, cols 64*wn
    const int bm = blockIdx.x, bn = blockIdx.y;

    // ---- prefetch chunk c into stage c&1 (8 x cp.async.16B per thread) ----
    auto prefetch = [&](int c) {
        const uint32_t st = sb + (uint32_t)(c & 1) * STAGE_B;
        const int kcol = c * GBK;
        #pragma unroll
        for (int q = 0; q < 2; q++) {
            const int u = tid + 256*q;
            const int r = u >> 2, sg = u & 3;
            const uint32_t so = (uint32_t)(r*LDT + sg*8) * 2;
            const size_t goA = (size_t)(bm*GBM + r) * H_ + kcol + sg*8;
            const size_t goB = (size_t)(bn*GBN + r) * H_ + kcol + sg*8;
            cp16(st + 0*MAT_B + so, Ahi + goA);
            cp16(st + 1*MAT_B + so, Alo + goA);
            cp16(st + 2*MAT_B + so, Bhi + goB);
            cp16(st + 3*MAT_B + so, Blo + goB);
        }
    };

    float acc[2][8][4];
    #pragma unroll
    for (int i = 0; i < 2; i++)
        #pragma unroll
        for (int j = 0; j < 8; j++)
            #pragma unroll
            for (int q = 0; q < 4; q++) acc[i][j][q] = 0.f;

    prefetch(0); CP_COMMIT();

    for (int c = 0; c < NKC; c++) {
        if (c + 1 < NKC) { prefetch(c + 1); CP_COMMIT(); CP_WAIT1(); }
        else             { CP_WAIT0(); }
        __syncthreads();

        const uint32_t st = sb + (uint32_t)(c & 1) * STAGE_B;
        #pragma unroll
        for (int ks = 0; ks < 2; ks++) {
            // A fragments (hi & lo): rows wm*32 + f*16 + lane%16, k seg lane/16
            uint32_t ah[8], al[8];
            #pragma unroll
            for (int f = 0; f < 2; f++) {
                const int row = wm*32 + f*16 + (lane & 15);
                const uint32_t off = (uint32_t)(row*LDT + ks*16 + (lane >> 4)*8) * 2;
                ldsm_x4(ah + 4*f, st + 0*MAT_B + off);
                ldsm_x4(al + 4*f, st + 1*MAT_B + off);
            }
            // B fragments loaded per 16-col group to keep register pressure
            // low (x4 -> two n8 frags), MMAs issued immediately after.
            #pragma unroll
            for (int p = 0; p < 4; p++) {
                uint32_t bh4[4], bl4[4];
                const int n  = wn*64 + p*16 + ((lane >> 4) << 3) + (lane & 7);
                const int kc = ks*16 + ((lane >> 3) & 1) * 8;
                const uint32_t off = (uint32_t)(n*LDT + kc) * 2;
                ldsm_x4(bh4, st + 2*MAT_B + off);
                ldsm_x4(bl4, st + 3*MAT_B + off);
                #pragma unroll
                for (int fm = 0; fm < 2; fm++)
                    #pragma unroll
                    for (int q = 0; q < 2; q++) {
                        float* a4 = acc[fm][2*p + q];
                        mma_bf16(a4, ah + 4*fm, bh4 + 2*q);
                        mma_bf16(a4, ah + 4*fm, bl4 + 2*q);
                        mma_bf16(a4, al + 4*fm, bh4 + 2*q);
                    }
            }
        }
        __syncthreads();
    }

    // ---- epilogue: acc + bias -> C ----
    #pragma unroll
    for (int fm = 0; fm < 2; fm++) {
        const int row = bm*GBM + wm*32 + fm*16 + (lane >> 2);
        #pragma unroll
        for (int fn = 0; fn < 8; fn++) {
            const int col = bn*GBN + wn*64 + fn*8 + (lane & 3)*2;
            const float2 bv = *reinterpret_cast<const float2*>(bias + col);
            float2 o0, o1;
            o0.x = acc[fm][fn][0] + bv.x; o0.y = acc[fm][fn][1] + bv.y;
            o1.x = acc[fm][fn][2] + bv.x; o1.y = acc[fm][fn][3] + bv.y;
            *reinterpret_cast<float2*>(C + (size_t)row     * Ndim + col) = o0;
            *reinterpret_cast<float2*>(C + (size_t)(row+8) * Ndim + col) = o1;
        }
    }
}

// ---------------- persistent scan kernel (unchanged, passing) --------------
#define SCAN_BLOCKS 128

__device__ __forceinline__ void grid_barrier(int nb) {
    __syncthreads();
    if (threadIdx.x == 0) {
        unsigned g = *((volatile unsigned*)&g_bar_gen);
        __threadfence();
        if (atomicAdd(&g_bar_count, 1) == (unsigned)(nb - 1)) {
            g_bar_count = 0;
            __threadfence();
            *((volatile unsigned*)&g_bar_gen) = g + 1;
        } else {
            while (*((volatile unsigned*)&g_bar_gen) == g) { __nanosleep(32); }
        }
        __threadfence();
    }
    __syncthreads();
}

__global__ __launch_bounds__(256)
void scan_kernel(const float* __restrict__ Whh, float* __restrict__ hfinal) {
    __shared__ __align__(16) float hsh[B_*H_];
    const int tid  = threadIdx.x;
    const int warp = tid >> 5;
    const int lane = tid & 31;
    const int j    = blockIdx.x * 8 + warp;

    float4 w[8];
    const float4* wrow = reinterpret_cast<const float4*>(Whh + (size_t)j * H_);
    #pragma unroll
    for (int i = 0; i < 8; i++) w[i] = wrow[lane + 32*i];

    for (int idx = blockIdx.x*256 + tid; idx < B_*H_; idx += SCAN_BLOCKS*256)
        g_h[idx] = 0.f;
    grid_barrier(SCAN_BLOCKS);

    for (int t = 0; t < T_; t++) {
        const int rp = t & 1, wp = rp ^ 1;
        float4* hs4 = reinterpret_cast<float4*>(hsh);
        const float4* hg4 = reinterpret_cast<const float4*>(g_h + rp*B_*H_);
        #pragma unroll
        for (int i = 0; i < (B_*H_/4)/256; i++) hs4[tid + 256*i] = hg4[tid + 256*i];
        __syncthreads();

        float acc[B_];
        #pragma unroll
        for (int b = 0; b < B_; b++) acc[b] = 0.f;
        #pragma unroll
        for (int i = 0; i < 8; i++) {
            const float4 wv = w[i];
            #pragma unroll
            for (int b = 0; b < B_; b++) {
                const float4 hv = *reinterpret_cast<const float4*>(&hsh[b*H_ + lane*4 + 128*i]);
                acc[b] += wv.x*hv.x + wv.y*hv.y + wv.z*hv.z + wv.w*hv.w;
            }
        }
        #pragma unroll
        for (int b = 0; b < B_; b++) {
            #pragma unroll
            for (int off = 16; off; off >>= 1)
                acc[b] += __shfl_xor_sync(0xffffffffu, acc[b], off);
        }
        if (lane < B_) {
            float a = acc[0];
            if (lane == 1) a = acc[1];
            if (lane == 2) a = acc[2];
            if (lane == 3) a = acc[3];
            if (lane == 4) a = acc[4];
            if (lane == 5) a = acc[5];
            if (lane == 6) a = acc[6];
            if (lane == 7) a = acc[7];
            const float hn = tanhf(a + g_pre[(size_t)lane*(T_*H_) + t*H_ + j]);
            g_h[wp*B_*H_ + lane*H_ + j] = hn;
            g_hs[(size_t)lane*(T_*H_) + t*H_ + j] = hn;
            if (t == T_-1) hfinal[lane*H_ + j] = hn;
        }
        __threadfence();
        grid_barrier(SCAN_BLOCKS);
    }
}

// ---------------- launch ----------------------------------------------------
extern "C" void kernel_launch(void* const* d_in, const int* in_sizes, int n_in,
                              void* d_out, int out_size) {
    const int*   x     = (const int*)  d_in[0];
    const float* embed = (const float*)d_in[1];
    const float* W_ih  = (const float*)d_in[2];
    const float* b_ih  = (const float*)d_in[3];
    const float* W_hh  = (const float*)d_in[4];
    const float* b_hh  = (const float*)d_in[5];
    const float* W_out = (const float*)d_in[6];
    const float* b_out = (const float*)d_in[7];
    float* out = (float*)d_out;

    void *p_Ahi, *p_Alo, *p_Wih_hi, *p_Wih_lo, *p_Wo_hi, *p_Wo_lo;
    void *p_Hhi, *p_Hlo, *p_pre, *p_hs, *p_bsum;
    cudaGetSymbolAddress(&p_Ahi, g_Ahi);       cudaGetSymbolAddress(&p_Alo, g_Alo);
    cudaGetSymbolAddress(&p_Wih_hi, g_Wih_hi); cudaGetSymbolAddress(&p_Wih_lo, g_Wih_lo);
    cudaGetSymbolAddress(&p_Wo_hi, g_Wo_hi);   cudaGetSymbolAddress(&p_Wo_lo, g_Wo_lo);
    cudaGetSymbolAddress(&p_Hhi, g_Hhi);       cudaGetSymbolAddress(&p_Hlo, g_Hlo);
    cudaGetSymbolAddress(&p_pre, g_pre);       cudaGetSymbolAddress(&p_hs, g_hs);
    cudaGetSymbolAddress(&p_bsum, g_bsum);

    cudaFuncSetAttribute(gemm_mma, cudaFuncAttributeMaxDynamicSharedMemorySize, SMEM_B);

    // 1) gather embeddings (split to bf16 hi/lo) + fused bias
    gather_kernel<<<M_ + 1, 256>>>(x, embed, b_ih, b_hh);

    // 2) split weights to bf16 hi/lo
    split_kernel<<<(H_*H_/4 + 255)/256, 256>>>(W_ih,
        (__nv_bfloat16*)p_Wih_hi, (__nv_bfloat16*)p_Wih_lo, (size_t)H_*H_);
    split_kernel<<<(int)(((size_t)V_*H_/4 + 255)/256), 256>>>(W_out,
        (__nv_bfloat16*)p_Wo_hi, (__nv_bfloat16*)p_Wo_lo, (size_t)V_*H_);

    // 3) pre = emb @ W_ih^T + (b_ih + b_hh)   [2048 x 1024]
    gemm_mma<<<dim3(M_/GBM, H_/GBN), 256, SMEM_B>>>(
        (const __nv_bfloat16*)p_Ahi, (const __nv_bfloat16*)p_Alo,
        (const __nv_bfloat16*)p_Wih_hi, (const __nv_bfloat16*)p_Wih_lo,
        (const float*)p_bsum, (float*)p_pre, H_);

    // 4) persistent recurrent scan; writes g_hs and h_final tail of d_out
    scan_kernel<<<SCAN_BLOCKS, 256>>>(W_hh, out + (size_t)M_ * V_);

    // 5) split hidden states to bf16 hi/lo
    split_kernel<<<(M_*H_/4 + 255)/256, 256>>>((const float*)p_hs,
        (__nv_bfloat16*)p_Hhi, (__nv_bfloat16*)p_Hlo, (size_t)M_*H_);

    // 6) outputs = hs @ W_out^T + b_out   [2048 x 32000]
    gemm_mma<<<dim3(M_/GBM, V_/GBN), 256, SMEM_B>>>(
        (const __nv_bfloat16*)p_Hhi, (const __nv_bfloat16*)p_Hlo,
        (const __nv_bfloat16*)p_Wo_hi, (const __nv_bfloat16*)p_Wo_lo,
        b_out, out, V_);
}